// round 2
// baseline (speedup 1.0000x reference)
#include <cuda_runtime.h>
#include <cuda_fp16.h>
#include <cstdint>

#define Mdim 8192
#define Kdim 4096
#define Ndim 4096

#define BM 128
#define BN 128
#define BK 64
#define NCHUNK (Kdim / BK)        // 64
#define THREADS 256

#define ABYTES (BM * BK * 2)      // 16384
#define BBYTES (BN * BK * 2)      // 16384
#define BUFBYTES (ABYTES + BBYTES)
#define SMEM_TOTAL (2 * BUFBYTES) // 65536

// ---------------- helpers ----------------

__device__ __forceinline__ uint32_t smem_u32(const void* p) {
    uint32_t a;
    asm("{ .reg .u64 t; cvta.to.shared.u64 t, %1; cvt.u32.u64 %0, t; }" : "=r"(a) : "l"(p));
    return a;
}

// one packed byte (in low byte of int32) -> fp16x2 {lo-8, hi-8}
// value = nibble - 8 (offset binary); fp16 magic: (0x6400 | u) == 1024+u
__device__ __forceinline__ uint32_t dec_h2(uint32_t w) {
    uint32_t r = (w & 0xFu) | ((w << 12) & 0x000F0000u) | 0x64006400u;
    __half2 h = __hsub2(*reinterpret_cast<__half2*>(&r),
                        __floats2half2_rn(1032.0f, 1032.0f));
    return *reinterpret_cast<uint32_t*>(&h);
}

__device__ __forceinline__ uint32_t h2u(__half2 v) {
    return *reinterpret_cast<uint32_t*>(&v);
}

__device__ __forceinline__ void ldsm4(uint32_t addr, uint32_t& r0, uint32_t& r1,
                                      uint32_t& r2, uint32_t& r3) {
    asm volatile("ldmatrix.sync.aligned.m8n8.x4.shared.b16 {%0,%1,%2,%3}, [%4];"
                 : "=r"(r0), "=r"(r1), "=r"(r2), "=r"(r3) : "r"(addr));
}

__device__ __forceinline__ void mma16816(float* d, const uint32_t* a, const uint32_t* b) {
    asm volatile(
        "mma.sync.aligned.m16n8k16.row.col.f32.f16.f16.f32 "
        "{%0,%1,%2,%3}, {%4,%5,%6,%7}, {%8,%9}, {%0,%1,%2,%3};"
        : "+f"(d[0]), "+f"(d[1]), "+f"(d[2]), "+f"(d[3])
        : "r"(a[0]), "r"(a[1]), "r"(a[2]), "r"(a[3]), "r"(b[0]), "r"(b[1]));
}

// ---------------- kernel ----------------

__global__ void __launch_bounds__(THREADS)
w4a16_mma_kernel(const float* __restrict__ x,
                 const int* __restrict__ wp,
                 const float* __restrict__ scales,
                 const float* __restrict__ bias,
                 float* __restrict__ out) {
    extern __shared__ char smem[];
    const uint32_t sb = smem_u32(smem);
    const int tid = threadIdx.x;
    const int lid = tid & 31;
    const int wid = tid >> 5;
    const int mw = wid & 3;    // warp row (4)
    const int nw = wid >> 2;   // warp col (2)
    const int m0 = blockIdx.y * BM;
    const int n0 = blockIdx.x * BN;

    // ldmatrix lane addressing (SW: 16B chunk c stored at c ^ (row&7))
    const int arow = mw * 32 + ((lid >> 3) & 1) * 8 + (lid & 7);
    const uint32_t aoff0 = (uint32_t)(arow * 128);
    const uint32_t aoff1 = (uint32_t)((arow + 16) * 128);
    const int arx = arow & 7;
    const int ah = lid >> 4;          // +chunk for A (k half)

    const int brow = nw * 64 + (lid >> 4) * 8 + (lid & 7);
    uint32_t boff[4];
#pragma unroll
    for (int p = 0; p < 4; ++p) boff[p] = (uint32_t)((brow + p * 16) * 128);
    const int brx = brow & 7;
    const int bh = (lid >> 3) & 1;    // +chunk for B (k half)

    // gmem staging mapping: 2 threads per tile row
    const int rowh = tid >> 1;
    const int half = tid & 1;
    const float* pa = x + (size_t)(m0 + rowh) * Kdim + half * 32;
    const int* pb = wp + (size_t)(n0 + rowh) * (Kdim / 2) + half * 16;
    const uint32_t srow = (uint32_t)(rowh * 128);
    const int rrx = rowh & 7;

    float acc[2][8][4];
#pragma unroll
    for (int i = 0; i < 2; ++i)
#pragma unroll
        for (int j = 0; j < 8; ++j)
#pragma unroll
            for (int c = 0; c < 4; ++c) acc[i][j][c] = 0.0f;

    float4 af[8];
    int4 bf[4];

    auto LOADG = [&](int kc) {
        const float4* p = reinterpret_cast<const float4*>(pa + kc * BK);
#pragma unroll
        for (int j = 0; j < 8; ++j) af[j] = __ldg(p + j);
        const int4* q = reinterpret_cast<const int4*>(pb + kc * (BK / 2));
#pragma unroll
        for (int j = 0; j < 4; ++j) bf[j] = __ldg(q + j);
    };

    auto STS = [&](int buf) {
        char* as = smem + buf * BUFBYTES;
        char* bs = as + ABYTES;
#pragma unroll
        for (int p = 0; p < 4; ++p) {
            float4 u = af[2 * p], v = af[2 * p + 1];
            uint4 val = make_uint4(h2u(__floats2half2_rn(u.x, u.y)),
                                   h2u(__floats2half2_rn(u.z, u.w)),
                                   h2u(__floats2half2_rn(v.x, v.y)),
                                   h2u(__floats2half2_rn(v.z, v.w)));
            uint32_t off = srow + (uint32_t)((((half * 4 + p) ^ rrx)) << 4);
            *reinterpret_cast<uint4*>(as + off) = val;
        }
#pragma unroll
        for (int p = 0; p < 4; ++p) {
            int4 wv = bf[p];
            uint4 val = make_uint4(dec_h2((uint32_t)wv.x), dec_h2((uint32_t)wv.y),
                                   dec_h2((uint32_t)wv.z), dec_h2((uint32_t)wv.w));
            uint32_t off = srow + (uint32_t)((((half * 4 + p) ^ rrx)) << 4);
            *reinterpret_cast<uint4*>(bs + off) = val;
        }
    };

    auto COMPUTE = [&](int buf) {
        const uint32_t ab = sb + buf * BUFBYTES;
        const uint32_t bb = ab + ABYTES;
#pragma unroll
        for (int ks = 0; ks < 4; ++ks) {
            uint32_t A[2][4], B[8][2];
            {
                uint32_t c = (uint32_t)((((2 * ks + ah) ^ arx)) << 4);
                ldsm4(ab + aoff0 + c, A[0][0], A[0][1], A[0][2], A[0][3]);
                ldsm4(ab + aoff1 + c, A[1][0], A[1][1], A[1][2], A[1][3]);
            }
#pragma unroll
            for (int p = 0; p < 4; ++p) {
                uint32_t c = (uint32_t)((((2 * ks + bh) ^ brx)) << 4);
                uint32_t r0, r1, r2, r3;
                ldsm4(bb + boff[p] + c, r0, r1, r2, r3);
                B[2 * p][0] = r0; B[2 * p][1] = r1;
                B[2 * p + 1][0] = r2; B[2 * p + 1][1] = r3;
            }
#pragma unroll
            for (int mt = 0; mt < 2; ++mt)
#pragma unroll
                for (int nt = 0; nt < 8; ++nt)
                    mma16816(acc[mt][nt], A[mt], B[nt]);
        }
    };

    // prologue
    LOADG(0);
    STS(0);
    __syncthreads();

#pragma unroll 1
    for (int kc = 0; kc < NCHUNK; ++kc) {
        if (kc + 1 < NCHUNK) LOADG(kc + 1);
        COMPUTE(kc & 1);
        if (kc + 1 < NCHUNK) STS((kc + 1) & 1);
        __syncthreads();
    }

    // epilogue: scale + bias, fp32 out
    const int er = lid >> 2;
    const int ec = (lid & 3) * 2;
#pragma unroll
    for (int nt = 0; nt < 8; ++nt) {
        const int col = n0 + nw * 64 + nt * 8 + ec;
        const float s0 = __ldg(scales + col), s1 = __ldg(scales + col + 1);
        const float bb0 = __ldg(bias + col), bb1 = __ldg(bias + col + 1);
#pragma unroll
        for (int mt = 0; mt < 2; ++mt) {
            const int row = m0 + mw * 32 + mt * 16 + er;
            float2 v0 = make_float2(acc[mt][nt][0] * s0 + bb0,
                                    acc[mt][nt][1] * s1 + bb1);
            *reinterpret_cast<float2*>(out + (size_t)row * Ndim + col) = v0;
            float2 v1 = make_float2(acc[mt][nt][2] * s0 + bb0,
                                    acc[mt][nt][3] * s1 + bb1);
            *reinterpret_cast<float2*>(out + (size_t)(row + 8) * Ndim + col) = v1;
        }
    }
}

// ---------------- launch ----------------

extern "C" void kernel_launch(void* const* d_in, const int* in_sizes, int n_in,
                              void* d_out, int out_size) {
    const float* x      = (const float*)d_in[0];   // [8192, 4096] fp32
    const int* wp       = (const int*)d_in[1];     // [4096, 2048] int32 (low byte = 2 nibbles)
    const float* scales = (const float*)d_in[2];   // [4096]
    const float* bias   = (const float*)d_in[3];   // [4096]
    float* out          = (float*)d_out;           // [8192, 4096] fp32

    cudaFuncSetAttribute(w4a16_mma_kernel,
                         cudaFuncAttributeMaxDynamicSharedMemorySize, SMEM_TOTAL);

    dim3 grid(Ndim / BN, Mdim / BM);  // (32, 64), N fastest -> x slice stays L2-hot
    w4a16_mma_kernel<<<grid, THREADS, SMEM_TOTAL>>>(x, wp, scales, bias, out);
}

// round 3
// speedup vs baseline: 3.0651x; 3.0651x over previous
#include <cuda_runtime.h>
#include <cuda_fp16.h>
#include <cstdint>

#define Mdim 8192
#define Kdim 4096
#define Ndim 4096

#define BM 128
#define BN 256
#define BK 64
#define NCHUNK (Kdim / BK)        // 64
#define THREADS 256
#define STAGES 3

#define ABYTES (BM * BK * 2)              // 16384
#define BBYTES (BN * BK * 2)              // 32768
#define STAGEB (ABYTES + BBYTES)          // 49152
#define SMEM_TOTAL (STAGES * STAGEB)      // 147456

// ---------------- scratch (allowed: __device__ globals) ----------------
__device__ __align__(16) __half Ah_buf[(size_t)Mdim * Kdim];  // 64 MB fp16 x
__device__ __align__(16) __half Bh_buf[(size_t)Ndim * Kdim];  // 32 MB fp16 W

// ---------------- helpers ----------------

__device__ __forceinline__ uint32_t smem_u32(const void* p) {
    uint32_t a;
    asm("{ .reg .u64 t; cvta.to.shared.u64 t, %1; cvt.u32.u64 %0, t; }" : "=r"(a) : "l"(p));
    return a;
}

__device__ __forceinline__ uint32_t h2u(__half2 v) {
    return *reinterpret_cast<uint32_t*>(&v);
}

// one packed byte (low byte of int32) -> fp16x2 {lo_nib-8, hi_nib-8}
__device__ __forceinline__ uint32_t dec_h2(uint32_t w) {
    uint32_t r = (w & 0xFu) | ((w << 12) & 0x000F0000u) | 0x64006400u;
    __half2 h = __hsub2(*reinterpret_cast<__half2*>(&r),
                        __floats2half2_rn(1032.0f, 1032.0f));
    return h2u(h);
}

__device__ __forceinline__ void ldsm4(uint32_t addr, uint32_t& r0, uint32_t& r1,
                                      uint32_t& r2, uint32_t& r3) {
    asm volatile("ldmatrix.sync.aligned.m8n8.x4.shared.b16 {%0,%1,%2,%3}, [%4];"
                 : "=r"(r0), "=r"(r1), "=r"(r2), "=r"(r3) : "r"(addr));
}

__device__ __forceinline__ void mma16816(float* d, const uint32_t* a, const uint32_t* b) {
    asm volatile(
        "mma.sync.aligned.m16n8k16.row.col.f32.f16.f16.f32 "
        "{%0,%1,%2,%3}, {%4,%5,%6,%7}, {%8,%9}, {%0,%1,%2,%3};"
        : "+f"(d[0]), "+f"(d[1]), "+f"(d[2]), "+f"(d[3])
        : "r"(a[0]), "r"(a[1]), "r"(a[2]), "r"(a[3]), "r"(b[0]), "r"(b[1]));
}

#define CP16(s, g) \
    asm volatile("cp.async.cg.shared.global [%0], [%1], 16;" :: "r"(s), "l"(g))
#define CP_COMMIT() asm volatile("cp.async.commit_group;" ::: "memory")
#define CP_WAIT1()  asm volatile("cp.async.wait_group 1;" ::: "memory")

// ---------------- prepass kernels ----------------

__global__ void __launch_bounds__(256) cvt_x_kernel(const float* __restrict__ x) {
    const size_t total = (size_t)Mdim * Kdim / 8;   // 8 floats per unit
    for (size_t i = (size_t)blockIdx.x * blockDim.x + threadIdx.x; i < total;
         i += (size_t)gridDim.x * blockDim.x) {
        const float4* p = reinterpret_cast<const float4*>(x) + 2 * i;
        float4 a = __ldg(p), b = __ldg(p + 1);
        uint4 v = make_uint4(h2u(__floats2half2_rn(a.x, a.y)),
                             h2u(__floats2half2_rn(a.z, a.w)),
                             h2u(__floats2half2_rn(b.x, b.y)),
                             h2u(__floats2half2_rn(b.z, b.w)));
        *(reinterpret_cast<uint4*>(Ah_buf) + i) = v;
    }
}

__global__ void __launch_bounds__(256) dec_w_kernel(const int* __restrict__ wp) {
    const size_t total = (size_t)Ndim * (Kdim / 2) / 4;  // 4 int32 per unit
    for (size_t i = (size_t)blockIdx.x * blockDim.x + threadIdx.x; i < total;
         i += (size_t)gridDim.x * blockDim.x) {
        int4 w = __ldg(reinterpret_cast<const int4*>(wp) + i);
        uint4 v = make_uint4(dec_h2((uint32_t)w.x), dec_h2((uint32_t)w.y),
                             dec_h2((uint32_t)w.z), dec_h2((uint32_t)w.w));
        *(reinterpret_cast<uint4*>(Bh_buf) + i) = v;
    }
}

// ---------------- main GEMM ----------------

__global__ void __launch_bounds__(THREADS)
w4a16_gemm_kernel(const float* __restrict__ scales,
                  const float* __restrict__ bias,
                  float* __restrict__ out) {
    extern __shared__ char smem[];
    const uint32_t sb = smem_u32(smem);
    const int tid = threadIdx.x;
    const int lid = tid & 31;
    const int wid = tid >> 5;
    const int mw = wid & 1;    // 2 warp rows
    const int nw = wid >> 1;   // 4 warp cols
    const int m0 = blockIdx.y * BM;
    const int n0 = blockIdx.x * BN;

    // ldmatrix lane addressing (chunk c of row r stored at (c ^ (r&7))*16)
    const int ar = mw * 64 + ((lid >> 3) & 1) * 8 + (lid & 7);
    uint32_t aoff[4];
#pragma unroll
    for (int t = 0; t < 4; ++t) aoff[t] = (uint32_t)((ar + t * 16) * 128);
    const int arx = ar & 7;
    const int ah = lid >> 4;

    const int br = nw * 64 + (lid >> 4) * 8 + (lid & 7);
    uint32_t boff[4];
#pragma unroll
    for (int p = 0; p < 4; ++p) boff[p] = (uint32_t)((br + p * 16) * 128);
    const int brx = br & 7;
    const int bh = (lid >> 3) & 1;

    // cp.async per-thread mapping (16B chunks, 8 per 128B row)
    const int arow = tid >> 3, ach = tid & 7;
    const __half* gA = Ah_buf + (size_t)(m0 + arow) * Kdim + ach * 8;      // +32 rows per i
    const uint32_t sA = (uint32_t)(arow * 128 + ((ach ^ (arow & 7)) << 4));
    const __half* gB = Bh_buf + (size_t)(n0 + arow) * Kdim + ach * 8;
    const uint32_t sB = (uint32_t)(ABYTES + arow * 128 + ((ach ^ (arow & 7)) << 4));

    float acc[4][8][4];
#pragma unroll
    for (int i = 0; i < 4; ++i)
#pragma unroll
        for (int j = 0; j < 8; ++j)
#pragma unroll
            for (int c = 0; c < 4; ++c) acc[i][j][c] = 0.0f;

    auto ISSUE = [&](int kc, int stage) {
        const uint32_t base = sb + stage * STAGEB;
        const __half* ga = gA + kc * BK;
#pragma unroll
        for (int i = 0; i < 4; ++i)   // 128 A rows / 32 rows-per-iter
            CP16(base + sA + i * 32 * 128, ga + (size_t)i * 32 * Kdim);
        const __half* gb = gB + kc * BK;
#pragma unroll
        for (int i = 0; i < 8; ++i)   // 256 B rows
            CP16(base + sB + i * 32 * 128, gb + (size_t)i * 32 * Kdim);
    };

    auto COMPUTE = [&](int stage) {
        const uint32_t ab = sb + stage * STAGEB;
        const uint32_t bb = ab + ABYTES;
#pragma unroll
        for (int ks = 0; ks < 4; ++ks) {
            uint32_t A[4][4], B[8][2];
            const uint32_t ca = (uint32_t)(((2 * ks + ah) ^ arx) << 4);
#pragma unroll
            for (int t = 0; t < 4; ++t)
                ldsm4(ab + aoff[t] + ca, A[t][0], A[t][1], A[t][2], A[t][3]);
            const uint32_t cb = (uint32_t)(((2 * ks + bh) ^ brx) << 4);
#pragma unroll
            for (int p = 0; p < 4; ++p) {
                uint32_t r0, r1, r2, r3;
                ldsm4(bb + boff[p] + cb, r0, r1, r2, r3);
                B[2 * p][0] = r0;     B[2 * p][1] = r1;
                B[2 * p + 1][0] = r2; B[2 * p + 1][1] = r3;
            }
#pragma unroll
            for (int mt = 0; mt < 4; ++mt)
#pragma unroll
                for (int nt = 0; nt < 8; ++nt)
                    mma16816(acc[mt][nt], A[mt], B[nt]);
        }
    };

    // prologue: 2 stages in flight
    ISSUE(0, 0); CP_COMMIT();
    ISSUE(1, 1); CP_COMMIT();

#pragma unroll 1
    for (int kc = 0; kc < NCHUNK; ++kc) {
        CP_WAIT1();           // group kc complete
        __syncthreads();
        if (kc + 2 < NCHUNK) ISSUE(kc + 2, (kc + 2) % STAGES);
        CP_COMMIT();
        COMPUTE(kc % STAGES);
        __syncthreads();      // compute done before stage reuse
    }

    // epilogue: scale + bias, fp32 out
    const int er = lid >> 2;
    const int ec = (lid & 3) * 2;
#pragma unroll
    for (int nt = 0; nt < 8; ++nt) {
        const int col = n0 + nw * 64 + nt * 8 + ec;
        const float s0 = __ldg(scales + col), s1 = __ldg(scales + col + 1);
        const float b0 = __ldg(bias + col), b1 = __ldg(bias + col + 1);
#pragma unroll
        for (int mt = 0; mt < 4; ++mt) {
            const int row = m0 + mw * 64 + mt * 16 + er;
            float2 v0 = make_float2(acc[mt][nt][0] * s0 + b0,
                                    acc[mt][nt][1] * s1 + b1);
            *reinterpret_cast<float2*>(out + (size_t)row * Ndim + col) = v0;
            float2 v1 = make_float2(acc[mt][nt][2] * s0 + b0,
                                    acc[mt][nt][3] * s1 + b1);
            *reinterpret_cast<float2*>(out + (size_t)(row + 8) * Ndim + col) = v1;
        }
    }
}

// ---------------- launch ----------------

extern "C" void kernel_launch(void* const* d_in, const int* in_sizes, int n_in,
                              void* d_out, int out_size) {
    const float* x      = (const float*)d_in[0];   // [8192, 4096] fp32
    const int* wp       = (const int*)d_in[1];     // [4096, 2048] int32
    const float* scales = (const float*)d_in[2];   // [4096]
    const float* bias   = (const float*)d_in[3];   // [4096]
    float* out          = (float*)d_out;           // [8192, 4096] fp32

    cvt_x_kernel<<<4096, 256>>>(x);
    dec_w_kernel<<<2048, 256>>>(wp);

    cudaFuncSetAttribute(w4a16_gemm_kernel,
                         cudaFuncAttributeMaxDynamicSharedMemorySize, SMEM_TOTAL);
    dim3 grid(Ndim / BN, Mdim / BM);  // (16, 64)
    w4a16_gemm_kernel<<<grid, THREADS, SMEM_TOTAL>>>(scales, bias, out);
}

// round 5
// speedup vs baseline: 3.1103x; 1.0147x over previous
#include <cuda_runtime.h>
#include <cuda_fp16.h>
#include <cstdint>

#define Mdim 8192
#define Kdim 4096
#define Ndim 4096

#define BM 128
#define BN 256
#define BK 64
#define NCHUNK (Kdim / BK)        // 64
#define THREADS 256
#define STAGES 4

#define ABYTES (BM * BK * 2)              // 16384
#define BBYTES (BN * BK * 2)              // 32768
#define STAGEB (ABYTES + BBYTES)          // 49152
#define SMEM_TOTAL (STAGES * STAGEB)      // 196608

// ---------------- scratch (allowed: __device__ globals) ----------------
__device__ __align__(16) __half Ah_buf[(size_t)Mdim * Kdim];  // 64 MB fp16 x
__device__ __align__(16) __half Bh_buf[(size_t)Ndim * Kdim];  // 32 MB fp16 W

// ---------------- helpers ----------------

__device__ __forceinline__ uint32_t smem_u32(const void* p) {
    uint32_t a;
    asm("{ .reg .u64 t; cvta.to.shared.u64 t, %1; cvt.u32.u64 %0, t; }" : "=r"(a) : "l"(p));
    return a;
}

__device__ __forceinline__ uint32_t h2u(__half2 v) {
    return *reinterpret_cast<uint32_t*>(&v);
}

// one packed byte (low byte of int32) -> fp16x2 {lo_nib-8, hi_nib-8}
__device__ __forceinline__ uint32_t dec_h2(uint32_t w) {
    uint32_t r = (w & 0xFu) | ((w << 12) & 0x000F0000u) | 0x64006400u;
    __half2 h = __hsub2(*reinterpret_cast<__half2*>(&r),
                        __floats2half2_rn(1032.0f, 1032.0f));
    return h2u(h);
}

__device__ __forceinline__ void ldsm4(uint32_t addr, uint32_t& r0, uint32_t& r1,
                                      uint32_t& r2, uint32_t& r3) {
    asm volatile("ldmatrix.sync.aligned.m8n8.x4.shared.b16 {%0,%1,%2,%3}, [%4];"
                 : "=r"(r0), "=r"(r1), "=r"(r2), "=r"(r3) : "r"(addr));
}

__device__ __forceinline__ void mma16816(float* d, const uint32_t* a, const uint32_t* b) {
    asm volatile(
        "mma.sync.aligned.m16n8k16.row.col.f32.f16.f16.f32 "
        "{%0,%1,%2,%3}, {%4,%5,%6,%7}, {%8,%9}, {%0,%1,%2,%3};"
        : "+f"(d[0]), "+f"(d[1]), "+f"(d[2]), "+f"(d[3])
        : "r"(a[0]), "r"(a[1]), "r"(a[2]), "r"(a[3]), "r"(b[0]), "r"(b[1]));
}

#define CP16(s, g) \
    asm volatile("cp.async.cg.shared.global [%0], [%1], 16;" :: "r"(s), "l"(g))
#define CP_COMMIT() asm volatile("cp.async.commit_group;" ::: "memory")
#define CP_WAIT2()  asm volatile("cp.async.wait_group 2;" ::: "memory")

// ---------------- prepass kernels ----------------

__global__ void __launch_bounds__(256) cvt_x_kernel(const float* __restrict__ x) {
    const size_t total = (size_t)Mdim * Kdim / 8;   // 8 floats per unit
    for (size_t i = (size_t)blockIdx.x * blockDim.x + threadIdx.x; i < total;
         i += (size_t)gridDim.x * blockDim.x) {
        const float4* p = reinterpret_cast<const float4*>(x) + 2 * i;
        float4 a = __ldg(p), b = __ldg(p + 1);
        uint4 v = make_uint4(h2u(__floats2half2_rn(a.x, a.y)),
                             h2u(__floats2half2_rn(a.z, a.w)),
                             h2u(__floats2half2_rn(b.x, b.y)),
                             h2u(__floats2half2_rn(b.z, b.w)));
        *(reinterpret_cast<uint4*>(Ah_buf) + i) = v;
    }
}

__global__ void __launch_bounds__(256) dec_w_kernel(const int* __restrict__ wp) {
    const size_t total = (size_t)Ndim * (Kdim / 2) / 4;  // 4 int32 per unit
    for (size_t i = (size_t)blockIdx.x * blockDim.x + threadIdx.x; i < total;
         i += (size_t)gridDim.x * blockDim.x) {
        int4 w = __ldg(reinterpret_cast<const int4*>(wp) + i);
        uint4 v = make_uint4(dec_h2((uint32_t)w.x), dec_h2((uint32_t)w.y),
                             dec_h2((uint32_t)w.z), dec_h2((uint32_t)w.w));
        *(reinterpret_cast<uint4*>(Bh_buf) + i) = v;
    }
}

// ---------------- main GEMM ----------------

__global__ void __launch_bounds__(THREADS)
w4a16_gemm_kernel(const float* __restrict__ scales,
                  const float* __restrict__ bias,
                  float* __restrict__ out) {
    extern __shared__ char smem[];
    const uint32_t sb = smem_u32(smem);
    const int tid = threadIdx.x;
    const int lid = tid & 31;
    const int wid = tid >> 5;
    const int mw = wid & 1;    // 2 warp rows
    const int nw = wid >> 1;   // 4 warp cols
    const int m0 = blockIdx.y * BM;
    const int n0 = blockIdx.x * BN;

    // ldmatrix lane addressing (chunk c of row r stored at (c ^ (r&7))*16)
    const int ar = mw * 64 + ((lid >> 3) & 1) * 8 + (lid & 7);
    uint32_t aoff[4];
#pragma unroll
    for (int t = 0; t < 4; ++t) aoff[t] = (uint32_t)((ar + t * 16) * 128);
    const int arx = ar & 7;
    const int ah = lid >> 4;

    const int br = nw * 64 + (lid >> 4) * 8 + (lid & 7);
    uint32_t boff[4];
#pragma unroll
    for (int p = 0; p < 4; ++p) boff[p] = (uint32_t)((br + p * 16) * 128);
    const int brx = br & 7;
    const int bh = (lid >> 3) & 1;

    // cp.async per-thread mapping (16B chunks, 8 per 128B row)
    const int arow = tid >> 3, ach = tid & 7;
    const __half* gA = Ah_buf + (size_t)(m0 + arow) * Kdim + ach * 8;      // +32 rows per i
    const uint32_t sA = (uint32_t)(arow * 128 + ((ach ^ (arow & 7)) << 4));
    const __half* gB = Bh_buf + (size_t)(n0 + arow) * Kdim + ach * 8;
    const uint32_t sB = (uint32_t)(ABYTES + arow * 128 + ((ach ^ (arow & 7)) << 4));

    float acc[4][8][4];
#pragma unroll
    for (int i = 0; i < 4; ++i)
#pragma unroll
        for (int j = 0; j < 8; ++j)
#pragma unroll
            for (int c = 0; c < 4; ++c) acc[i][j][c] = 0.0f;

    auto ISSUE = [&](int kc, int stage) {
        const uint32_t base = sb + stage * STAGEB;
        const __half* ga = gA + kc * BK;
#pragma unroll
        for (int i = 0; i < 4; ++i)   // 128 A rows / 32 rows-per-iter
            CP16(base + sA + i * 32 * 128, ga + (size_t)i * 32 * Kdim);
        const __half* gb = gB + kc * BK;
#pragma unroll
        for (int i = 0; i < 8; ++i)   // 256 B rows
            CP16(base + sB + i * 32 * 128, gb + (size_t)i * 32 * Kdim);
    };

    auto COMPUTE = [&](int stage) {
        const uint32_t ab = sb + stage * STAGEB;
        const uint32_t bb = ab + ABYTES;
#pragma unroll
        for (int ks = 0; ks < 4; ++ks) {
            uint32_t A[4][4], B[8][2];
            const uint32_t ca = (uint32_t)(((2 * ks + ah) ^ arx) << 4);
#pragma unroll
            for (int t = 0; t < 4; ++t)
                ldsm4(ab + aoff[t] + ca, A[t][0], A[t][1], A[t][2], A[t][3]);
            const uint32_t cb = (uint32_t)(((2 * ks + bh) ^ brx) << 4);
#pragma unroll
            for (int p = 0; p < 4; ++p) {
                uint32_t r0, r1, r2, r3;
                ldsm4(bb + boff[p] + cb, r0, r1, r2, r3);
                B[2 * p][0] = r0;     B[2 * p][1] = r1;
                B[2 * p + 1][0] = r2; B[2 * p + 1][1] = r3;
            }
#pragma unroll
            for (int mt = 0; mt < 4; ++mt)
#pragma unroll
                for (int nt = 0; nt < 8; ++nt)
                    mma16816(acc[mt][nt], A[mt], B[nt]);
        }
    };

    // prologue: 3 stages in flight
    ISSUE(0, 0); CP_COMMIT();
    ISSUE(1, 1); CP_COMMIT();
    ISSUE(2, 2); CP_COMMIT();

#pragma unroll 1
    for (int kc = 0; kc < NCHUNK; ++kc) {
        CP_WAIT2();           // group kc complete (<=2 groups still pending)
        __syncthreads();      // also proves all warps finished COMPUTE(kc-1)
        if (kc + 3 < NCHUNK) {
            ISSUE(kc + 3, (kc + 3) % STAGES);  // overwrites stage (kc-1)%4: safe
            CP_COMMIT();
        }
        COMPUTE(kc % STAGES);
    }

    // epilogue: scale + bias, fp32 out
    const int er = lid >> 2;
    const int ec = (lid & 3) * 2;
#pragma unroll
    for (int nt = 0; nt < 8; ++nt) {
        const int col = n0 + nw * 64 + nt * 8 + ec;
        const float s0 = __ldg(scales + col), s1 = __ldg(scales + col + 1);
        const float b0 = __ldg(bias + col), b1 = __ldg(bias + col + 1);
#pragma unroll
        for (int mt = 0; mt < 4; ++mt) {
            const int row = m0 + mw * 64 + mt * 16 + er;
            float2 v0 = make_float2(acc[mt][nt][0] * s0 + b0,
                                    acc[mt][nt][1] * s1 + b1);
            *reinterpret_cast<float2*>(out + (size_t)row * Ndim + col) = v0;
            float2 v1 = make_float2(acc[mt][nt][2] * s0 + b0,
                                    acc[mt][nt][3] * s1 + b1);
            *reinterpret_cast<float2*>(out + (size_t)(row + 8) * Ndim + col) = v1;
        }
    }
}

// ---------------- launch ----------------

extern "C" void kernel_launch(void* const* d_in, const int* in_sizes, int n_in,
                              void* d_out, int out_size) {
    const float* x      = (const float*)d_in[0];   // [8192, 4096] fp32
    const int* wp       = (const int*)d_in[1];     // [4096, 2048] int32
    const float* scales = (const float*)d_in[2];   // [4096]
    const float* bias   = (const float*)d_in[3];   // [4096]
    float* out          = (float*)d_out;           // [8192, 4096] fp32

    cvt_x_kernel<<<4096, 256>>>(x);
    dec_w_kernel<<<2048, 256>>>(wp);

    cudaFuncSetAttribute(w4a16_gemm_kernel,
                         cudaFuncAttributeMaxDynamicSharedMemorySize, SMEM_TOTAL);
    dim3 grid(Ndim / BN, Mdim / BM);  // (16, 64)
    w4a16_gemm_kernel<<<grid, THREADS, SMEM_TOTAL>>>(scales, bias, out);
}